// round 1
// baseline (speedup 1.0000x reference)
#include <cuda_runtime.h>
#include <cuda_bf16.h>

// Problem constants (fixed by the dataset)
#define NN 50000
#define EE 850000
#define DIN 128
#define D1 64
#define H1 8
#define D2 16

// ---------------- scratch (__device__ globals; no allocation allowed) ----------
__device__ float    g_z1[NN * D1];
__device__ float    g_as1[NN * H1];
__device__ float    g_ad1[NN * H1];
__device__ unsigned g_ms1[H1];
__device__ unsigned g_md1[H1];
__device__ int      g_counts[NN];
__device__ int      g_rowptr[NN + 1];
__device__ int      g_cursor[NN];
__device__ int      g_csr[EE];
__device__ float    g_h[NN * D1];
__device__ float    g_z2[NN * D2];
__device__ float    g_as2[NN];
__device__ float    g_ad2[NN];
__device__ unsigned g_ms2;
__device__ unsigned g_md2;

// ordered-int encoding for float atomicMax
__device__ __forceinline__ unsigned fenc(float f) {
    unsigned u = __float_as_uint(f);
    return (u & 0x80000000u) ? ~u : (u | 0x80000000u);
}
__device__ __forceinline__ float fdec(unsigned u) {
    return __uint_as_float((u & 0x80000000u) ? (u & 0x7fffffffu) : ~u);
}
__device__ __forceinline__ float leaky(float e) { return e > 0.f ? e : 0.2f * e; }

// ---------------- init: zero counts + max slots --------------------------------
__global__ void init_kernel(int N) {
    int i = blockIdx.x * blockDim.x + threadIdx.x;
    if (i < N) g_counts[i] = 0;
    if (i < H1) { g_ms1[i] = 0u; g_md1[i] = 0u; }
    if (i == 0) { g_ms2 = 0u; g_md2 = 0u; }
}

// ---------------- GEMM1: z1 = x @ W1; per-node alphas; global per-head maxes ---
// 256 threads / block; 64 nodes / block; thread = (node_local, quarter q of 16 cols)
__global__ void gemm1_kernel(const float* __restrict__ x,
                             const float* __restrict__ W1,
                             const float* __restrict__ a_src1,
                             const float* __restrict__ a_dst1,
                             int N) {
    __shared__ float sW[DIN * D1];   // 32 KB
    __shared__ unsigned sMax[2 * H1];
    int t = threadIdx.x;
    for (int i = t; i < DIN * D1 / 4; i += 256)
        ((float4*)sW)[i] = ((const float4*)W1)[i];
    if (t < 2 * H1) sMax[t] = 0u;
    __syncthreads();

    int nl = t >> 2;          // node within block
    int q  = t & 3;           // column quarter: cols q*16 .. q*16+15
    int n  = blockIdx.x * 64 + nl;

    if (n < N) {
        float acc[16];
#pragma unroll
        for (int i = 0; i < 16; i++) acc[i] = 0.f;
        const float4* xr4 = (const float4*)(x + (size_t)n * DIN);
#pragma unroll 4
        for (int k4 = 0; k4 < 32; k4++) {
            float4 xv = __ldg(xr4 + k4);
            float xs[4] = {xv.x, xv.y, xv.z, xv.w};
#pragma unroll
            for (int kk = 0; kk < 4; kk++) {
                const float4* w = (const float4*)&sW[(k4 * 4 + kk) * D1 + q * 16];
                float4 w0 = w[0], w1 = w[1], w2 = w[2], w3 = w[3];
                float xsv = xs[kk];
                acc[0]  += xsv * w0.x; acc[1]  += xsv * w0.y; acc[2]  += xsv * w0.z; acc[3]  += xsv * w0.w;
                acc[4]  += xsv * w1.x; acc[5]  += xsv * w1.y; acc[6]  += xsv * w1.z; acc[7]  += xsv * w1.w;
                acc[8]  += xsv * w2.x; acc[9]  += xsv * w2.y; acc[10] += xsv * w2.z; acc[11] += xsv * w2.w;
                acc[12] += xsv * w3.x; acc[13] += xsv * w3.y; acc[14] += xsv * w3.z; acc[15] += xsv * w3.w;
            }
        }
        // write z1
        float4* zr = (float4*)&g_z1[(size_t)n * D1 + q * 16];
        zr[0] = make_float4(acc[0], acc[1], acc[2], acc[3]);
        zr[1] = make_float4(acc[4], acc[5], acc[6], acc[7]);
        zr[2] = make_float4(acc[8], acc[9], acc[10], acc[11]);
        zr[3] = make_float4(acc[12], acc[13], acc[14], acc[15]);
        // alphas for heads 2q, 2q+1 (each head = 8 contiguous cols)
        int h0 = 2 * q;
        float as0 = 0.f, ad0 = 0.f, as1v = 0.f, ad1v = 0.f;
#pragma unroll
        for (int d = 0; d < 8; d++) {
            as0  += acc[d]     * a_src1[h0 * 8 + d];
            ad0  += acc[d]     * a_dst1[h0 * 8 + d];
            as1v += acc[8 + d] * a_src1[(h0 + 1) * 8 + d];
            ad1v += acc[8 + d] * a_dst1[(h0 + 1) * 8 + d];
        }
        g_as1[n * H1 + h0]     = as0;
        g_as1[n * H1 + h0 + 1] = as1v;
        g_ad1[n * H1 + h0]     = ad0;
        g_ad1[n * H1 + h0 + 1] = ad1v;
        atomicMax(&sMax[h0],          fenc(as0));
        atomicMax(&sMax[h0 + 1],      fenc(as1v));
        atomicMax(&sMax[H1 + h0],     fenc(ad0));
        atomicMax(&sMax[H1 + h0 + 1], fenc(ad1v));
    }
    __syncthreads();
    if (t < H1)             atomicMax(&g_ms1[t], sMax[t]);
    else if (t < 2 * H1)    atomicMax(&g_md1[t - H1], sMax[t]);
}

// ---------------- CSR build ----------------------------------------------------
__global__ void hist_kernel(const int* __restrict__ dst, int E) {
    int i = blockIdx.x * blockDim.x + threadIdx.x;
    if (i < E) atomicAdd(&g_counts[dst[i]], 1);
}

__global__ void scan_kernel(int N) {
    __shared__ int s[1024];
    int t = threadIdx.x;
    int chunk = (N + 1023) >> 10;
    int lo = t * chunk;
    int hi = lo + chunk; if (hi > N) hi = N;
    int sum = 0;
    for (int i = lo; i < hi; i++) sum += g_counts[i];
    s[t] = sum;
    __syncthreads();
    for (int off = 1; off < 1024; off <<= 1) {
        int v = (t >= off) ? s[t - off] : 0;
        __syncthreads();
        s[t] += v;
        __syncthreads();
    }
    int base = (t == 0) ? 0 : s[t - 1];
    for (int i = lo; i < hi; i++) {
        g_rowptr[i] = base;
        g_cursor[i] = base;
        base += g_counts[i];
    }
    if (t == 1023) g_rowptr[N] = s[1023];
}

__global__ void scatter_kernel(const int* __restrict__ src,
                               const int* __restrict__ dst, int E) {
    int i = blockIdx.x * blockDim.x + threadIdx.x;
    if (i < E) {
        int d = dst[i];
        int p = atomicAdd(&g_cursor[d], 1);
        g_csr[p] = src[i];
    }
}

// ---------------- layer-1 aggregation: one warp per dst node --------------------
// lane c handles output dims c and c+32. heads: h0 = c>>3 (0..3), h1 = 4 + (c>>3).
__global__ void agg1_kernel(const float* __restrict__ b1, int N) {
    int w = (blockIdx.x * blockDim.x + threadIdx.x) >> 5;
    int lane = threadIdx.x & 31;
    if (w >= N) return;
    int n = w;
    int h0 = lane >> 3;
    int h1 = 4 + h0;

    float M_l = 0.f, ad_l = 0.f;
    if (lane < H1) {
        M_l  = fdec(g_ms1[lane]) + fdec(g_md1[lane]);
        ad_l = g_ad1[n * H1 + lane];
    }

    float acc0 = 0.f, acc1 = 0.f, den = 0.f;
    int beg = g_rowptr[n], end = g_rowptr[n + 1];
    int s = (beg < end) ? g_csr[beg] : 0;
    for (int i = beg; i < end; i++) {
        int s_next = (i + 1 < end) ? g_csr[i + 1] : 0;
        float wv = 0.f;
        if (lane < H1) {
            float e = leaky(g_as1[s * H1 + lane] + ad_l);
            wv = __expf(e - M_l);
            den += wv;
        }
        float w0 = __shfl_sync(0xffffffffu, wv, h0);
        float w1 = __shfl_sync(0xffffffffu, wv, h1);
        acc0 += w0 * g_z1[(size_t)s * D1 + lane];
        acc1 += w1 * g_z1[(size_t)s * D1 + 32 + lane];
        s = s_next;
    }
    float d0 = __shfl_sync(0xffffffffu, den, h0);
    float d1 = __shfl_sync(0xffffffffu, den, h1);
    float o0 = acc0 / (d0 + 1e-16f) + b1[lane];
    float o1 = acc1 / (d1 + 1e-16f) + b1[lane + 32];
    o0 = o0 > 0.f ? o0 : (__expf(o0) - 1.f);   // ELU
    o1 = o1 > 0.f ? o1 : (__expf(o1) - 1.f);
    g_h[(size_t)n * D1 + lane]      = o0;
    g_h[(size_t)n * D1 + 32 + lane] = o1;
}

// ---------------- layer-2 node transform: z2 = h @ W2, alphas, global max ------
// 16 threads per node.
__global__ void node2_kernel(const float* __restrict__ W2,
                             const float* __restrict__ a_src2,
                             const float* __restrict__ a_dst2,
                             int N) {
    __shared__ unsigned smS, smD;
    if (threadIdx.x == 0) { smS = 0u; smD = 0u; }
    __syncthreads();

    int g = blockIdx.x * blockDim.x + threadIdx.x;
    int n = g >> 4;
    int c = g & 15;
    if (n < N) {
        float acc = 0.f;
        const float* hr = &g_h[(size_t)n * D1];
#pragma unroll 8
        for (int k = 0; k < D1; k++)
            acc += __ldg(hr + k) * W2[k * D2 + c];
        g_z2[n * D2 + c] = acc;
        float ts = acc * a_src2[c];
        float td = acc * a_dst2[c];
#pragma unroll
        for (int off = 8; off > 0; off >>= 1) {
            ts += __shfl_xor_sync(0xffffffffu, ts, off, 16);
            td += __shfl_xor_sync(0xffffffffu, td, off, 16);
        }
        if (c == 0) {
            g_as2[n] = ts;
            g_ad2[n] = td;
            atomicMax(&smS, fenc(ts));
            atomicMax(&smD, fenc(td));
        }
    }
    __syncthreads();
    if (threadIdx.x == 0) {
        atomicMax(&g_ms2, smS);
        atomicMax(&g_md2, smD);
    }
}

// ---------------- layer-2 aggregation + output ---------------------------------
// 16 threads per node.
__global__ void agg2_kernel(const float* __restrict__ b2,
                            float* __restrict__ out, int N) {
    int g = blockIdx.x * blockDim.x + threadIdx.x;
    int n = g >> 4;
    int c = g & 15;
    if (n >= N) return;
    float M2 = fdec(g_ms2) + fdec(g_md2);
    float adl = g_ad2[n];
    float acc = 0.f, den = 0.f;
    int beg = g_rowptr[n], end = g_rowptr[n + 1];
    int s = (beg < end) ? g_csr[beg] : 0;
    for (int i = beg; i < end; i++) {
        int s_next = (i + 1 < end) ? g_csr[i + 1] : 0;
        float wv = 0.f;
        if (c == 0) {
            float e = leaky(g_as2[s] + adl);
            wv = __expf(e - M2);
            den += wv;
        }
        wv = __shfl_sync(0xffffffffu, wv, 0, 16);
        acc += wv * g_z2[s * D2 + c];
        s = s_next;
    }
    den = __shfl_sync(0xffffffffu, den, 0, 16);
    out[n * D2 + c] = acc / (den + 1e-16f) + b2[c];
}

// ---------------- launch --------------------------------------------------------
static inline int cdiv(int a, int b) { return (a + b - 1) / b; }

extern "C" void kernel_launch(void* const* d_in, const int* in_sizes, int n_in,
                              void* d_out, int out_size) {
    const float* x   = (const float*)d_in[0];
    const int*   ei  = (const int*)d_in[1];
    const float* W1  = (const float*)d_in[2];
    const float* as1 = (const float*)d_in[3];
    const float* ad1 = (const float*)d_in[4];
    const float* b1  = (const float*)d_in[5];
    const float* W2  = (const float*)d_in[6];
    const float* as2 = (const float*)d_in[7];
    const float* ad2 = (const float*)d_in[8];
    const float* b2  = (const float*)d_in[9];
    float* out = (float*)d_out;

    int N = in_sizes[0] / DIN;
    int E = in_sizes[1] / 2;
    const int* src = ei;
    const int* dst = ei + E;

    init_kernel<<<cdiv(N, 256), 256>>>(N);
    gemm1_kernel<<<cdiv(N, 64), 256>>>(x, W1, as1, ad1, N);
    hist_kernel<<<cdiv(E, 256), 256>>>(dst, E);
    scan_kernel<<<1, 1024>>>(N);
    scatter_kernel<<<cdiv(E, 256), 256>>>(src, dst, E);
    agg1_kernel<<<cdiv(N * 32, 256), 256>>>(b1, N);
    node2_kernel<<<cdiv(N * 16, 256), 256>>>(W2, as2, ad2, N);
    agg2_kernel<<<cdiv(N * 16, 256), 256>>>(b2, out, N);
}

// round 2
// speedup vs baseline: 1.4825x; 1.4825x over previous
#include <cuda_runtime.h>
#include <cuda_bf16.h>

// Problem constants (fixed by the dataset)
#define NN 50000
#define EE 850000
#define DIN 128
#define D1 64
#define H1 8
#define D2 16
#define NBMAX 256   // max scan blocks (ceil(50000/256)=196)

// ---------------- scratch (__device__ globals; no allocation allowed) ----------
__device__ float    g_z1[NN * D1];
__device__ float    g_as1[NN * H1];
__device__ float    g_ad1[NN * H1];
__device__ unsigned g_ms1[H1];
__device__ unsigned g_md1[H1];
__device__ int      g_counts[NN];
__device__ int      g_rowptr[NN + 1];
__device__ int      g_cursor[NN];
__device__ int      g_csr[EE];
__device__ int      g_bsum[NBMAX];
__device__ int      g_boff[NBMAX];
__device__ float    g_h[NN * D1];
__device__ float    g_z2[NN * D2];
__device__ float    g_as2[NN];
__device__ float    g_ad2[NN];
__device__ unsigned g_ms2;
__device__ unsigned g_md2;

// ordered-int encoding for float atomicMax
__device__ __forceinline__ unsigned fenc(float f) {
    unsigned u = __float_as_uint(f);
    return (u & 0x80000000u) ? ~u : (u | 0x80000000u);
}
__device__ __forceinline__ float fdec(unsigned u) {
    return __uint_as_float((u & 0x80000000u) ? (u & 0x7fffffffu) : ~u);
}
__device__ __forceinline__ float leaky(float e) { return e > 0.f ? e : 0.2f * e; }

// ---------------- init: zero counts + max slots --------------------------------
__global__ void init_kernel(int N) {
    int i = blockIdx.x * blockDim.x + threadIdx.x;
    if (i < N) g_counts[i] = 0;
    if (i < H1) { g_ms1[i] = 0u; g_md1[i] = 0u; }
    if (i == 0) { g_ms2 = 0u; g_md2 = 0u; }
}

// ---------------- GEMM1: z1 = x @ W1; per-node alphas; global per-head maxes ---
__global__ void gemm1_kernel(const float* __restrict__ x,
                             const float* __restrict__ W1,
                             const float* __restrict__ a_src1,
                             const float* __restrict__ a_dst1,
                             int N) {
    __shared__ float sW[DIN * D1];   // 32 KB
    __shared__ unsigned sMax[2 * H1];
    int t = threadIdx.x;
    for (int i = t; i < DIN * D1 / 4; i += 256)
        ((float4*)sW)[i] = ((const float4*)W1)[i];
    if (t < 2 * H1) sMax[t] = 0u;
    __syncthreads();

    int nl = t >> 2;          // node within block
    int q  = t & 3;           // column quarter: cols q*16 .. q*16+15
    int n  = blockIdx.x * 64 + nl;

    if (n < N) {
        float acc[16];
#pragma unroll
        for (int i = 0; i < 16; i++) acc[i] = 0.f;
        const float4* xr4 = (const float4*)(x + (size_t)n * DIN);
#pragma unroll 4
        for (int k4 = 0; k4 < 32; k4++) {
            float4 xv = __ldg(xr4 + k4);
            float xs[4] = {xv.x, xv.y, xv.z, xv.w};
#pragma unroll
            for (int kk = 0; kk < 4; kk++) {
                const float4* w = (const float4*)&sW[(k4 * 4 + kk) * D1 + q * 16];
                float4 w0 = w[0], w1 = w[1], w2 = w[2], w3 = w[3];
                float xsv = xs[kk];
                acc[0]  += xsv * w0.x; acc[1]  += xsv * w0.y; acc[2]  += xsv * w0.z; acc[3]  += xsv * w0.w;
                acc[4]  += xsv * w1.x; acc[5]  += xsv * w1.y; acc[6]  += xsv * w1.z; acc[7]  += xsv * w1.w;
                acc[8]  += xsv * w2.x; acc[9]  += xsv * w2.y; acc[10] += xsv * w2.z; acc[11] += xsv * w2.w;
                acc[12] += xsv * w3.x; acc[13] += xsv * w3.y; acc[14] += xsv * w3.w == 0.f ? 0.f : xsv * w3.z, acc[14] += 0.f; // placeholder removed below
            }
        }
        // (note: see corrected loop below)
    }
}

// The above gemm1 got mangled during edit; real one follows.
__global__ void gemm1_real_kernel(const float* __restrict__ x,
                                  const float* __restrict__ W1,
                                  const float* __restrict__ a_src1,
                                  const float* __restrict__ a_dst1,
                                  int N) {
    __shared__ float sW[DIN * D1];   // 32 KB
    __shared__ unsigned sMax[2 * H1];
    int t = threadIdx.x;
    for (int i = t; i < DIN * D1 / 4; i += 256)
        ((float4*)sW)[i] = ((const float4*)W1)[i];
    if (t < 2 * H1) sMax[t] = 0u;
    __syncthreads();

    int nl = t >> 2;
    int q  = t & 3;
    int n  = blockIdx.x * 64 + nl;

    if (n < N) {
        float acc[16];
#pragma unroll
        for (int i = 0; i < 16; i++) acc[i] = 0.f;
        const float4* xr4 = (const float4*)(x + (size_t)n * DIN);
#pragma unroll 4
        for (int k4 = 0; k4 < 32; k4++) {
            float4 xv = __ldg(xr4 + k4);
            float xs[4] = {xv.x, xv.y, xv.z, xv.w};
#pragma unroll
            for (int kk = 0; kk < 4; kk++) {
                const float4* w = (const float4*)&sW[(k4 * 4 + kk) * D1 + q * 16];
                float4 w0 = w[0], w1 = w[1], w2 = w[2], w3 = w[3];
                float xsv = xs[kk];
                acc[0]  += xsv * w0.x; acc[1]  += xsv * w0.y; acc[2]  += xsv * w0.z; acc[3]  += xsv * w0.w;
                acc[4]  += xsv * w1.x; acc[5]  += xsv * w1.y; acc[6]  += xsv * w1.z; acc[7]  += xsv * w1.w;
                acc[8]  += xsv * w2.x; acc[9]  += xsv * w2.y; acc[10] += xsv * w2.z; acc[11] += xsv * w2.w;
                acc[12] += xsv * w3.x; acc[13] += xsv * w3.y; acc[14] += xsv * w3.z; acc[15] += xsv * w3.w;
            }
        }
        float4* zr = (float4*)&g_z1[(size_t)n * D1 + q * 16];
        zr[0] = make_float4(acc[0], acc[1], acc[2], acc[3]);
        zr[1] = make_float4(acc[4], acc[5], acc[6], acc[7]);
        zr[2] = make_float4(acc[8], acc[9], acc[10], acc[11]);
        zr[3] = make_float4(acc[12], acc[13], acc[14], acc[15]);
        int h0 = 2 * q;
        float as0 = 0.f, ad0 = 0.f, as1v = 0.f, ad1v = 0.f;
#pragma unroll
        for (int d = 0; d < 8; d++) {
            as0  += acc[d]     * a_src1[h0 * 8 + d];
            ad0  += acc[d]     * a_dst1[h0 * 8 + d];
            as1v += acc[8 + d] * a_src1[(h0 + 1) * 8 + d];
            ad1v += acc[8 + d] * a_dst1[(h0 + 1) * 8 + d];
        }
        g_as1[n * H1 + h0]     = as0;
        g_as1[n * H1 + h0 + 1] = as1v;
        g_ad1[n * H1 + h0]     = ad0;
        g_ad1[n * H1 + h0 + 1] = ad1v;
        atomicMax(&sMax[h0],          fenc(as0));
        atomicMax(&sMax[h0 + 1],      fenc(as1v));
        atomicMax(&sMax[H1 + h0],     fenc(ad0));
        atomicMax(&sMax[H1 + h0 + 1], fenc(ad1v));
    }
    __syncthreads();
    if (t < H1)             atomicMax(&g_ms1[t], sMax[t]);
    else if (t < 2 * H1)    atomicMax(&g_md1[t - H1], sMax[t]);
}

// ---------------- CSR build ----------------------------------------------------
__global__ void hist_kernel(const int* __restrict__ dst, int E) {
    int i = blockIdx.x * blockDim.x + threadIdx.x;
    if (i < E) atomicAdd(&g_counts[dst[i]], 1);
}

// Phase A: per-block sums of counts (256 elems / block)
__global__ void scanA_kernel(int N) {
    __shared__ int s[256];
    int t = threadIdx.x;
    int i = blockIdx.x * 256 + t;
    s[t] = (i < N) ? g_counts[i] : 0;
    __syncthreads();
#pragma unroll
    for (int off = 128; off > 0; off >>= 1) {
        if (t < off) s[t] += s[t + off];
        __syncthreads();
    }
    if (t == 0) g_bsum[blockIdx.x] = s[0];
}

// Phase B: exclusive scan of block sums (single block)
__global__ void scanB_kernel(int NB) {
    __shared__ int s[256];
    int t = threadIdx.x;
    int v = (t < NB) ? g_bsum[t] : 0;
    s[t] = v;
    __syncthreads();
#pragma unroll
    for (int off = 1; off < 256; off <<= 1) {
        int u = (t >= off) ? s[t - off] : 0;
        __syncthreads();
        s[t] += u;
        __syncthreads();
    }
    if (t < NB) g_boff[t] = s[t] - v;
}

// Phase C: local exclusive scan + block offset -> rowptr/cursor
__global__ void scanC_kernel(int N) {
    __shared__ int s[256];
    int t = threadIdx.x;
    int i = blockIdx.x * 256 + t;
    int v = (i < N) ? g_counts[i] : 0;
    s[t] = v;
    __syncthreads();
#pragma unroll
    for (int off = 1; off < 256; off <<= 1) {
        int u = (t >= off) ? s[t - off] : 0;
        __syncthreads();
        s[t] += u;
        __syncthreads();
    }
    int incl = s[t];
    int base = g_boff[blockIdx.x];
    if (i < N) {
        int r = base + incl - v;
        g_rowptr[i] = r;
        g_cursor[i] = r;
        if (i == N - 1) g_rowptr[N] = base + incl;
    }
}

__global__ void scatter_kernel(const int* __restrict__ src,
                               const int* __restrict__ dst, int E) {
    int i = blockIdx.x * blockDim.x + threadIdx.x;
    if (i < E) {
        int d = dst[i];
        int p = atomicAdd(&g_cursor[d], 1);
        g_csr[p] = src[i];
    }
}

// ---------------- layer-1 aggregation: one warp per dst node --------------------
// lane c handles output dims c and c+32. heads: h0 = c>>3 (0..3), h1 = 4 + (c>>3).
__global__ void agg1_kernel(const float* __restrict__ b1, int N) {
    int w = (blockIdx.x * blockDim.x + threadIdx.x) >> 5;
    int lane = threadIdx.x & 31;
    if (w >= N) return;
    int n = w;
    int h0 = lane >> 3;
    int h1 = 4 + h0;

    float M_l = 0.f, ad_l = 0.f;
    if (lane < H1) {
        M_l  = fdec(g_ms1[lane]) + fdec(g_md1[lane]);
        ad_l = g_ad1[n * H1 + lane];
    }

    float acc0 = 0.f, acc1 = 0.f, den = 0.f;
    int beg = g_rowptr[n], end = g_rowptr[n + 1];
    int i = beg;

    // unrolled-by-4 main loop: batch loads to raise MLP
    for (; i + 4 <= end; i += 4) {
        int s0 = g_csr[i], s1 = g_csr[i + 1], s2 = g_csr[i + 2], s3 = g_csr[i + 3];
        float a0 = 0.f, a1 = 0.f, a2 = 0.f, a3 = 0.f;
        if (lane < H1) {
            a0 = g_as1[s0 * H1 + lane];
            a1 = g_as1[s1 * H1 + lane];
            a2 = g_as1[s2 * H1 + lane];
            a3 = g_as1[s3 * H1 + lane];
        }
        float z0a = g_z1[(size_t)s0 * D1 + lane],      z0b = g_z1[(size_t)s0 * D1 + 32 + lane];
        float z1a = g_z1[(size_t)s1 * D1 + lane],      z1b = g_z1[(size_t)s1 * D1 + 32 + lane];
        float z2a = g_z1[(size_t)s2 * D1 + lane],      z2b = g_z1[(size_t)s2 * D1 + 32 + lane];
        float z3a = g_z1[(size_t)s3 * D1 + lane],      z3b = g_z1[(size_t)s3 * D1 + 32 + lane];

        float w0v = 0.f, w1v = 0.f, w2v = 0.f, w3v = 0.f;
        if (lane < H1) {
            w0v = __expf(leaky(a0 + ad_l) - M_l);
            w1v = __expf(leaky(a1 + ad_l) - M_l);
            w2v = __expf(leaky(a2 + ad_l) - M_l);
            w3v = __expf(leaky(a3 + ad_l) - M_l);
            den += (w0v + w1v) + (w2v + w3v);
        }
        acc0 += __shfl_sync(0xffffffffu, w0v, h0) * z0a;
        acc1 += __shfl_sync(0xffffffffu, w0v, h1) * z0b;
        acc0 += __shfl_sync(0xffffffffu, w1v, h0) * z1a;
        acc1 += __shfl_sync(0xffffffffu, w1v, h1) * z1b;
        acc0 += __shfl_sync(0xffffffffu, w2v, h0) * z2a;
        acc1 += __shfl_sync(0xffffffffu, w2v, h1) * z2b;
        acc0 += __shfl_sync(0xffffffffu, w3v, h0) * z3a;
        acc1 += __shfl_sync(0xffffffffu, w3v, h1) * z3b;
    }
    // remainder
    for (; i < end; i++) {
        int s = g_csr[i];
        float wv = 0.f;
        if (lane < H1) {
            float e = leaky(g_as1[s * H1 + lane] + ad_l);
            wv = __expf(e - M_l);
            den += wv;
        }
        acc0 += __shfl_sync(0xffffffffu, wv, h0) * g_z1[(size_t)s * D1 + lane];
        acc1 += __shfl_sync(0xffffffffu, wv, h1) * g_z1[(size_t)s * D1 + 32 + lane];
    }

    float d0 = __shfl_sync(0xffffffffu, den, h0);
    float d1 = __shfl_sync(0xffffffffu, den, h1);
    float o0 = acc0 / (d0 + 1e-16f) + b1[lane];
    float o1 = acc1 / (d1 + 1e-16f) + b1[lane + 32];
    o0 = o0 > 0.f ? o0 : (__expf(o0) - 1.f);   // ELU
    o1 = o1 > 0.f ? o1 : (__expf(o1) - 1.f);
    g_h[(size_t)n * D1 + lane]      = o0;
    g_h[(size_t)n * D1 + 32 + lane] = o1;
}

// ---------------- layer-2 node transform: z2 = h @ W2, alphas, global max ------
__global__ void node2_kernel(const float* __restrict__ W2,
                             const float* __restrict__ a_src2,
                             const float* __restrict__ a_dst2,
                             int N) {
    __shared__ unsigned smS, smD;
    if (threadIdx.x == 0) { smS = 0u; smD = 0u; }
    __syncthreads();

    int g = blockIdx.x * blockDim.x + threadIdx.x;
    int n = g >> 4;
    int c = g & 15;
    if (n < N) {
        float acc = 0.f;
        const float* hr = &g_h[(size_t)n * D1];
#pragma unroll 8
        for (int k = 0; k < D1; k++)
            acc += __ldg(hr + k) * W2[k * D2 + c];
        g_z2[n * D2 + c] = acc;
        float ts = acc * a_src2[c];
        float td = acc * a_dst2[c];
#pragma unroll
        for (int off = 8; off > 0; off >>= 1) {
            ts += __shfl_xor_sync(0xffffffffu, ts, off, 16);
            td += __shfl_xor_sync(0xffffffffu, td, off, 16);
        }
        if (c == 0) {
            g_as2[n] = ts;
            g_ad2[n] = td;
            atomicMax(&smS, fenc(ts));
            atomicMax(&smD, fenc(td));
        }
    }
    __syncthreads();
    if (threadIdx.x == 0) {
        atomicMax(&g_ms2, smS);
        atomicMax(&g_md2, smD);
    }
}

// ---------------- layer-2 aggregation + output ---------------------------------
__global__ void agg2_kernel(const float* __restrict__ b2,
                            float* __restrict__ out, int N) {
    int g = blockIdx.x * blockDim.x + threadIdx.x;
    int n = g >> 4;
    int c = g & 15;
    if (n >= N) return;
    float M2 = fdec(g_ms2) + fdec(g_md2);
    float adl = g_ad2[n];
    float acc = 0.f, den = 0.f;
    int beg = g_rowptr[n], end = g_rowptr[n + 1];
    int i = beg;
    for (; i + 4 <= end; i += 4) {
        int s0 = g_csr[i], s1 = g_csr[i + 1], s2 = g_csr[i + 2], s3 = g_csr[i + 3];
        float a0 = 0.f, a1 = 0.f, a2 = 0.f, a3 = 0.f;
        if (c == 0) {
            a0 = g_as2[s0]; a1 = g_as2[s1]; a2 = g_as2[s2]; a3 = g_as2[s3];
        }
        float z0 = g_z2[s0 * D2 + c];
        float z1 = g_z2[s1 * D2 + c];
        float z2 = g_z2[s2 * D2 + c];
        float z3 = g_z2[s3 * D2 + c];
        float w0 = 0.f, w1 = 0.f, w2 = 0.f, w3 = 0.f;
        if (c == 0) {
            w0 = __expf(leaky(a0 + adl) - M2);
            w1 = __expf(leaky(a1 + adl) - M2);
            w2 = __expf(leaky(a2 + adl) - M2);
            w3 = __expf(leaky(a3 + adl) - M2);
            den += (w0 + w1) + (w2 + w3);
        }
        acc += __shfl_sync(0xffffffffu, w0, 0, 16) * z0;
        acc += __shfl_sync(0xffffffffu, w1, 0, 16) * z1;
        acc += __shfl_sync(0xffffffffu, w2, 0, 16) * z2;
        acc += __shfl_sync(0xffffffffu, w3, 0, 16) * z3;
    }
    for (; i < end; i++) {
        int s = g_csr[i];
        float wv = 0.f;
        if (c == 0) {
            float e = leaky(g_as2[s] + adl);
            wv = __expf(e - M2);
            den += wv;
        }
        acc += __shfl_sync(0xffffffffu, wv, 0, 16) * g_z2[s * D2 + c];
    }
    den = __shfl_sync(0xffffffffu, den, 0, 16);
    out[n * D2 + c] = acc / (den + 1e-16f) + b2[c];
}

// ---------------- launch --------------------------------------------------------
static inline int cdiv(int a, int b) { return (a + b - 1) / b; }

extern "C" void kernel_launch(void* const* d_in, const int* in_sizes, int n_in,
                              void* d_out, int out_size) {
    const float* x   = (const float*)d_in[0];
    const int*   ei  = (const int*)d_in[1];
    const float* W1  = (const float*)d_in[2];
    const float* as1 = (const float*)d_in[3];
    const float* ad1 = (const float*)d_in[4];
    const float* b1  = (const float*)d_in[5];
    const float* W2  = (const float*)d_in[6];
    const float* as2 = (const float*)d_in[7];
    const float* ad2 = (const float*)d_in[8];
    const float* b2  = (const float*)d_in[9];
    float* out = (float*)d_out;

    int N = in_sizes[0] / DIN;
    int E = in_sizes[1] / 2;
    const int* src = ei;
    const int* dst = ei + E;
    int NB = cdiv(N, 256);

    init_kernel<<<cdiv(N, 256), 256>>>(N);
    gemm1_real_kernel<<<cdiv(N, 64), 256>>>(x, W1, as1, ad1, N);
    hist_kernel<<<cdiv(E, 256), 256>>>(dst, E);
    scanA_kernel<<<NB, 256>>>(N);
    scanB_kernel<<<1, 256>>>(NB);
    scanC_kernel<<<NB, 256>>>(N);
    scatter_kernel<<<cdiv(E, 256), 256>>>(src, dst, E);
    agg1_kernel<<<cdiv(N * 32, 256), 256>>>(b1, N);
    node2_kernel<<<cdiv(N * 16, 256), 256>>>(W2, as2, ad2, N);
    agg2_kernel<<<cdiv(N * 16, 256), 256>>>(b2, out, N);
}

// round 3
// speedup vs baseline: 2.2633x; 1.5267x over previous
#include <cuda_runtime.h>
#include <cuda_bf16.h>

// Problem constants (fixed by the dataset)
#define NN 50000
#define EE 850000
#define DIN 128
#define D1 64
#define H1 8
#define D2 16
#define NBMAX 256

// ---------------- scratch (__device__ globals) ---------------------------------
__device__ float    g_z1[NN * D1];
__device__ float    g_as1[NN * H1];
__device__ float    g_ad1[NN * H1];
__device__ unsigned g_ms1[H1];
__device__ unsigned g_md1[H1];
__device__ int      g_counts[NN];
__device__ int      g_rowptr[NN + 1];
__device__ int      g_cursor[NN];
__device__ int      g_csr[EE];
__device__ int      g_bsum[NBMAX];
__device__ int      g_boff[NBMAX];
__device__ float    g_h[NN * D1];
__device__ float    g_z2[NN * D2];
__device__ float    g_as2[NN];
__device__ float    g_ad2[NN];
__device__ unsigned g_ms2;
__device__ unsigned g_md2;

__device__ __forceinline__ unsigned fenc(float f) {
    unsigned u = __float_as_uint(f);
    return (u & 0x80000000u) ? ~u : (u | 0x80000000u);
}
__device__ __forceinline__ float fdec(unsigned u) {
    return __uint_as_float((u & 0x80000000u) ? (u & 0x7fffffffu) : ~u);
}
__device__ __forceinline__ float leaky(float e) { return e > 0.f ? e : 0.2f * e; }
__device__ __forceinline__ float dot4(float4 a, float4 b) {
    return a.x * b.x + a.y * b.y + a.z * b.z + a.w * b.w;
}

// ---------------- init ----------------------------------------------------------
__global__ void init_kernel(int N) {
    int i = blockIdx.x * blockDim.x + threadIdx.x;
    if (i < N) g_counts[i] = 0;
    if (i < H1) { g_ms1[i] = 0u; g_md1[i] = 0u; }
    if (i == 0) { g_ms2 = 0u; g_md2 = 0u; }
}

// ---------------- GEMM1: 256-node tile, 4 nodes/thread, k-chunked smem ---------
__global__ __launch_bounds__(256, 2)
void gemm1_kernel(const float* __restrict__ x,
                  const float* __restrict__ W1,
                  const float* __restrict__ a_src1,
                  const float* __restrict__ a_dst1,
                  int N) {
    __shared__ float sX[256 * 33];      // 256 nodes x 32 k, pad 33
    __shared__ float sW[32 * 64];       // k-chunk x 64 cols
    __shared__ unsigned sMax[16];
    int t = threadIdx.x;
    if (t < 16) sMax[t] = 0u;
    int base = blockIdx.x << 8;
    int nl = t >> 2;      // 0..63
    int q  = t & 3;       // column quarter

    float4 acc[4][4];
#pragma unroll
    for (int i = 0; i < 4; i++)
#pragma unroll
        for (int j = 0; j < 4; j++) acc[i][j] = make_float4(0.f, 0.f, 0.f, 0.f);

    for (int kc = 0; kc < 4; kc++) {
        __syncthreads();
        // stage W chunk: 32 rows x 64 cols = 512 float4
#pragma unroll
        for (int i = 0; i < 2; i++)
            ((float4*)sW)[t + (i << 8)] =
                __ldg((const float4*)(W1 + (kc << 11)) + t + (i << 8));
        // stage X chunk: 256 nodes x 32 k = 2048 float4
#pragma unroll
        for (int i = 0; i < 8; i++) {
            int idx = t + (i << 8);
            int node = idx >> 3, k4 = idx & 7;
            int n = base + node;
            float4 v = make_float4(0.f, 0.f, 0.f, 0.f);
            if (n < N) v = __ldg((const float4*)x + ((size_t)n << 5) + (kc << 3) + k4);
            float* dp = &sX[node * 33 + (k4 << 2)];
            dp[0] = v.x; dp[1] = v.y; dp[2] = v.z; dp[3] = v.w;
        }
        __syncthreads();
#pragma unroll 8
        for (int k = 0; k < 32; k++) {
            const float4* wr = (const float4*)&sW[(k << 6) + (q << 4)];
            float4 w0 = wr[0], w1 = wr[1], w2 = wr[2], w3 = wr[3];
#pragma unroll
            for (int i = 0; i < 4; i++) {
                float xv = sX[(nl + (i << 6)) * 33 + k];
                acc[i][0].x += xv * w0.x; acc[i][0].y += xv * w0.y;
                acc[i][0].z += xv * w0.z; acc[i][0].w += xv * w0.w;
                acc[i][1].x += xv * w1.x; acc[i][1].y += xv * w1.y;
                acc[i][1].z += xv * w1.z; acc[i][1].w += xv * w1.w;
                acc[i][2].x += xv * w2.x; acc[i][2].y += xv * w2.y;
                acc[i][2].z += xv * w2.z; acc[i][2].w += xv * w2.w;
                acc[i][3].x += xv * w3.x; acc[i][3].y += xv * w3.y;
                acc[i][3].z += xv * w3.z; acc[i][3].w += xv * w3.w;
            }
        }
    }

    // epilogue: write z1, alphas, per-head maxes
    int h0 = q << 1;
    const float4* As4 = (const float4*)a_src1;
    const float4* Ad4 = (const float4*)a_dst1;
    float4 s0 = __ldg(&As4[h0 * 2]),     s1 = __ldg(&As4[h0 * 2 + 1]);
    float4 s2 = __ldg(&As4[h0 * 2 + 2]), s3 = __ldg(&As4[h0 * 2 + 3]);
    float4 d0 = __ldg(&Ad4[h0 * 2]),     d1 = __ldg(&Ad4[h0 * 2 + 1]);
    float4 d2 = __ldg(&Ad4[h0 * 2 + 2]), d3 = __ldg(&Ad4[h0 * 2 + 3]);
#pragma unroll
    for (int i = 0; i < 4; i++) {
        int n = base + nl + (i << 6);
        if (n < N) {
            float4* zr = (float4*)&g_z1[((size_t)n << 6) + (q << 4)];
            zr[0] = acc[i][0]; zr[1] = acc[i][1];
            zr[2] = acc[i][2]; zr[3] = acc[i][3];
            float as0  = dot4(acc[i][0], s0) + dot4(acc[i][1], s1);
            float as1v = dot4(acc[i][2], s2) + dot4(acc[i][3], s3);
            float ad0  = dot4(acc[i][0], d0) + dot4(acc[i][1], d1);
            float ad1v = dot4(acc[i][2], d2) + dot4(acc[i][3], d3);
            g_as1[n * H1 + h0]     = as0;
            g_as1[n * H1 + h0 + 1] = as1v;
            g_ad1[n * H1 + h0]     = ad0;
            g_ad1[n * H1 + h0 + 1] = ad1v;
            atomicMax(&sMax[h0],         fenc(as0));
            atomicMax(&sMax[h0 + 1],     fenc(as1v));
            atomicMax(&sMax[8 + h0],     fenc(ad0));
            atomicMax(&sMax[8 + h0 + 1], fenc(ad1v));
        }
    }
    __syncthreads();
    if (t < 8)        atomicMax(&g_ms1[t], sMax[t]);
    else if (t < 16)  atomicMax(&g_md1[t - 8], sMax[t]);
}

// ---------------- CSR build ----------------------------------------------------
__global__ void hist_kernel(const int* __restrict__ dst, int E) {
    int i = blockIdx.x * blockDim.x + threadIdx.x;
    int i4 = i << 2;
    if (i4 + 3 < E) {
        int4 d = __ldg((const int4*)dst + i);
        atomicAdd(&g_counts[d.x], 1);
        atomicAdd(&g_counts[d.y], 1);
        atomicAdd(&g_counts[d.z], 1);
        atomicAdd(&g_counts[d.w], 1);
    } else {
        for (int j = i4; j < E && j < i4 + 4; j++)
            atomicAdd(&g_counts[dst[j]], 1);
    }
}

__global__ void scanA_kernel(int N) {
    __shared__ int s[256];
    int t = threadIdx.x;
    int i = blockIdx.x * 256 + t;
    s[t] = (i < N) ? g_counts[i] : 0;
    __syncthreads();
#pragma unroll
    for (int off = 128; off > 0; off >>= 1) {
        if (t < off) s[t] += s[t + off];
        __syncthreads();
    }
    if (t == 0) g_bsum[blockIdx.x] = s[0];
}

__global__ void scanB_kernel(int NB) {
    __shared__ int s[256];
    int t = threadIdx.x;
    int v = (t < NB) ? g_bsum[t] : 0;
    s[t] = v;
    __syncthreads();
#pragma unroll
    for (int off = 1; off < 256; off <<= 1) {
        int u = (t >= off) ? s[t - off] : 0;
        __syncthreads();
        s[t] += u;
        __syncthreads();
    }
    if (t < NB) g_boff[t] = s[t] - v;
}

__global__ void scanC_kernel(int N) {
    __shared__ int s[256];
    int t = threadIdx.x;
    int i = blockIdx.x * 256 + t;
    int v = (i < N) ? g_counts[i] : 0;
    s[t] = v;
    __syncthreads();
#pragma unroll
    for (int off = 1; off < 256; off <<= 1) {
        int u = (t >= off) ? s[t - off] : 0;
        __syncthreads();
        s[t] += u;
        __syncthreads();
    }
    int incl = s[t];
    int base = g_boff[blockIdx.x];
    if (i < N) {
        int r = base + incl - v;
        g_rowptr[i] = r;
        g_cursor[i] = r;
        if (i == N - 1) g_rowptr[N] = base + incl;
    }
}

__global__ void scatter_kernel(const int* __restrict__ src,
                               const int* __restrict__ dst, int E) {
    int i = blockIdx.x * blockDim.x + threadIdx.x;
    int i4 = i << 2;
    if (i4 + 3 < E) {
        int4 sv = __ldg((const int4*)src + i);
        int4 dv = __ldg((const int4*)dst + i);
        g_csr[atomicAdd(&g_cursor[dv.x], 1)] = sv.x;
        g_csr[atomicAdd(&g_cursor[dv.y], 1)] = sv.y;
        g_csr[atomicAdd(&g_cursor[dv.z], 1)] = sv.z;
        g_csr[atomicAdd(&g_cursor[dv.w], 1)] = sv.w;
    } else {
        for (int j = i4; j < E && j < i4 + 4; j++)
            g_csr[atomicAdd(&g_cursor[dst[j]], 1)] = src[j];
    }
}

// ---------------- layer-1 aggregation: warp/node, cooperative + float4 ---------
__global__ void agg1_kernel(const float* __restrict__ b1, int N) {
    int w = (blockIdx.x * blockDim.x + threadIdx.x) >> 5;
    int lane = threadIdx.x & 31;
    if (w >= N) return;
    int n = w;
    int h8 = lane & 7;       // head for attention phase
    int grp = lane >> 3;     // edge slot (0..3) for attention phase
    int half = lane >> 4;    // edge parity for message phase
    int c = lane & 15;       // float4 owner: dims 4c..4c+3
    int hq = c >> 1;         // head of dims 4c..4c+3

    float ad_rep = g_ad1[n * H1 + h8];
    float M_rep  = fdec(g_ms1[h8]) + fdec(g_md1[h8]);

    float4 acc = make_float4(0.f, 0.f, 0.f, 0.f);
    float den = 0.f;
    int beg = g_rowptr[n], end = g_rowptr[n + 1];

    for (int i = beg; i < end; i += 4) {
        int e = i + grp;
        bool v = e < end;
        int s_g = v ? __ldg(&g_csr[e]) : 0;
        float wv = 0.f;
        if (v) {
            float a = __ldg(&g_as1[s_g * H1 + h8]);
            wv = __expf(leaky(a + ad_rep) - M_rep);
        }
        den += wv;
#pragma unroll
        for (int p = 0; p < 2; p++) {
            int eidx = (p << 1) + half;                              // 0..3
            int s_e  = __shfl_sync(0xffffffffu, s_g, eidx << 3);
            float we = __shfl_sync(0xffffffffu, wv, (eidx << 3) | hq);
            float4 z = __ldg((const float4*)&g_z1[((size_t)s_e << 6) + (c << 2)]);
            acc.x += we * z.x; acc.y += we * z.y;
            acc.z += we * z.z; acc.w += we * z.w;
        }
    }
    // combine halves
    acc.x += __shfl_xor_sync(0xffffffffu, acc.x, 16);
    acc.y += __shfl_xor_sync(0xffffffffu, acc.y, 16);
    acc.z += __shfl_xor_sync(0xffffffffu, acc.z, 16);
    acc.w += __shfl_xor_sync(0xffffffffu, acc.w, 16);
    // reduce den across edge groups (same head stride 8)
    den += __shfl_xor_sync(0xffffffffu, den, 8);
    den += __shfl_xor_sync(0xffffffffu, den, 16);
    float dl = __shfl_sync(0xffffffffu, den, hq);

    if (lane < 16) {
        float4 bb = __ldg((const float4*)&b1[c << 2]);
        float inv = 1.f / (dl + 1e-16f);
        float o0 = acc.x * inv + bb.x;
        float o1 = acc.y * inv + bb.y;
        float o2 = acc.z * inv + bb.z;
        float o3 = acc.w * inv + bb.w;
        o0 = o0 > 0.f ? o0 : (__expf(o0) - 1.f);
        o1 = o1 > 0.f ? o1 : (__expf(o1) - 1.f);
        o2 = o2 > 0.f ? o2 : (__expf(o2) - 1.f);
        o3 = o3 > 0.f ? o3 : (__expf(o3) - 1.f);
        *(float4*)&g_h[((size_t)n << 6) + (c << 2)] = make_float4(o0, o1, o2, o3);
    }
}

// ---------------- layer-2 node transform (smem-staged) --------------------------
__global__ void node2_kernel(const float* __restrict__ W2,
                             const float* __restrict__ a_src2,
                             const float* __restrict__ a_dst2,
                             int N) {
    __shared__ float sH[16 * 64];
    __shared__ float sW2[64 * 16];
    __shared__ unsigned smS, smD;
    int t = threadIdx.x;
    if (t == 0) { smS = 0u; smD = 0u; }
    int base = blockIdx.x << 4;
    {
        int node = t >> 4, k4 = t & 15;
        int nn = base + node;
        float4 v = make_float4(0.f, 0.f, 0.f, 0.f);
        if (nn < N) v = __ldg((const float4*)&g_h[((size_t)nn << 6) + (k4 << 2)]);
        *(float4*)&sH[(node << 6) + (k4 << 2)] = v;
        ((float4*)sW2)[t] = __ldg((const float4*)W2 + t);
    }
    __syncthreads();

    int nl = t >> 4, c = t & 15;
    int n = base + nl;
    float acc = 0.f;
#pragma unroll 16
    for (int k = 0; k < 64; k++)
        acc += sH[(nl << 6) + k] * sW2[(k << 4) + c];

    float ts = acc * __ldg(&a_src2[c]);
    float td = acc * __ldg(&a_dst2[c]);
#pragma unroll
    for (int off = 8; off > 0; off >>= 1) {
        ts += __shfl_xor_sync(0xffffffffu, ts, off, 16);
        td += __shfl_xor_sync(0xffffffffu, td, off, 16);
    }
    if (n < N) {
        g_z2[n * D2 + c] = acc;
        if (c == 0) {
            g_as2[n] = ts;
            g_ad2[n] = td;
            atomicMax(&smS, fenc(ts));
            atomicMax(&smD, fenc(td));
        }
    }
    __syncthreads();
    if (t == 0) {
        atomicMax(&g_ms2, smS);
        atomicMax(&g_md2, smD);
    }
}

// ---------------- layer-2 aggregation: warp/node, 8 edges/iter ------------------
__global__ void agg2_kernel(const float* __restrict__ b2,
                            float* __restrict__ out, int N) {
    int w = (blockIdx.x * blockDim.x + threadIdx.x) >> 5;
    int lane = threadIdx.x & 31;
    if (w >= N) return;
    int n = w;
    int e8 = lane & 7;       // edge slot for attention
    int g  = lane >> 2;      // edge (0..7) for message phase
    int cq = lane & 3;       // float4 owner: dims 4cq..4cq+3

    float M2  = fdec(g_ms2) + fdec(g_md2);
    float adl = g_ad2[n];
    float4 acc = make_float4(0.f, 0.f, 0.f, 0.f);
    float den = 0.f;
    int beg = g_rowptr[n], end = g_rowptr[n + 1];

    for (int i = beg; i < end; i += 8) {
        int e = i + e8;
        bool v = e < end;
        int s_l = v ? __ldg(&g_csr[e]) : 0;
        float wv = 0.f;
        if (v) wv = __expf(leaky(__ldg(&g_as2[s_l]) + adl) - M2);
        if (lane < 8) den += wv;
        int s_e  = __shfl_sync(0xffffffffu, s_l, g);
        float we = __shfl_sync(0xffffffffu, wv, g);
        float4 z = __ldg((const float4*)&g_z2[(size_t)s_e * D2 + (cq << 2)]);
        acc.x += we * z.x; acc.y += we * z.y;
        acc.z += we * z.z; acc.w += we * z.w;
    }
#pragma unroll
    for (int off = 4; off < 32; off <<= 1) {
        acc.x += __shfl_xor_sync(0xffffffffu, acc.x, off);
        acc.y += __shfl_xor_sync(0xffffffffu, acc.y, off);
        acc.z += __shfl_xor_sync(0xffffffffu, acc.z, off);
        acc.w += __shfl_xor_sync(0xffffffffu, acc.w, off);
    }
    den += __shfl_xor_sync(0xffffffffu, den, 1);
    den += __shfl_xor_sync(0xffffffffu, den, 2);
    den += __shfl_xor_sync(0xffffffffu, den, 4);
    den = __shfl_sync(0xffffffffu, den, 0);

    if (lane < 4) {
        float4 bb = __ldg((const float4*)&b2[cq << 2]);
        float inv = 1.f / (den + 1e-16f);
        float4 o = make_float4(acc.x * inv + bb.x, acc.y * inv + bb.y,
                               acc.z * inv + bb.z, acc.w * inv + bb.w);
        *(float4*)&out[(size_t)n * D2 + (cq << 2)] = o;
    }
}

// ---------------- launch --------------------------------------------------------
static inline int cdiv(int a, int b) { return (a + b - 1) / b; }

extern "C" void kernel_launch(void* const* d_in, const int* in_sizes, int n_in,
                              void* d_out, int out_size) {
    const float* x   = (const float*)d_in[0];
    const int*   ei  = (const int*)d_in[1];
    const float* W1  = (const float*)d_in[2];
    const float* as1 = (const float*)d_in[3];
    const float* ad1 = (const float*)d_in[4];
    const float* b1  = (const float*)d_in[5];
    const float* W2  = (const float*)d_in[6];
    const float* as2 = (const float*)d_in[7];
    const float* ad2 = (const float*)d_in[8];
    const float* b2  = (const float*)d_in[9];
    float* out = (float*)d_out;

    int N = in_sizes[0] / DIN;
    int E = in_sizes[1] / 2;
    const int* src = ei;
    const int* dst = ei + E;
    int NB = cdiv(N, 256);
    int E4 = cdiv(E, 4);

    init_kernel<<<cdiv(N, 256), 256>>>(N);
    gemm1_kernel<<<cdiv(N, 256), 256>>>(x, W1, as1, ad1, N);
    hist_kernel<<<cdiv(E4, 256), 256>>>(dst, E);
    scanA_kernel<<<NB, 256>>>(N);
    scanB_kernel<<<1, 256>>>(NB);
    scanC_kernel<<<NB, 256>>>(N);
    scatter_kernel<<<cdiv(E4, 256), 256>>>(src, dst, E);
    agg1_kernel<<<cdiv(N * 32, 256), 256>>>(b1, N);
    node2_kernel<<<cdiv(N, 16), 256>>>(W2, as2, ad2, N);
    agg2_kernel<<<cdiv(N * 32, 256), 256>>>(b2, out, N);
}

// round 4
// speedup vs baseline: 2.8204x; 1.2461x over previous
#include <cuda_runtime.h>
#include <cuda_bf16.h>

// Problem constants (fixed by the dataset)
#define NN 50000
#define EE 850000
#define DIN 128
#define D1 64
#define H1 8
#define D2 16
#define NBMAX 256

// ---------------- scratch (__device__ globals) ---------------------------------
__device__ float    g_z1[NN * D1];
__device__ float    g_as1[NN * H1];
__device__ float    g_ad1[NN * H1];
__device__ unsigned g_ms1[H1];
__device__ unsigned g_md1[H1];
__device__ int      g_counts[NN];
__device__ int      g_rowptr[NN + 1];
__device__ int      g_cursor[NN];
__device__ int      g_csr[EE];
__device__ int      g_bsum[NBMAX];
__device__ int      g_boff[NBMAX];
__device__ float    g_h[NN * D1];
__device__ float    g_z2[NN * D2];
__device__ float    g_as2[NN];
__device__ float    g_ad2[NN];
__device__ unsigned g_ms2;
__device__ unsigned g_md2;

__device__ __forceinline__ unsigned fenc(float f) {
    unsigned u = __float_as_uint(f);
    return (u & 0x80000000u) ? ~u : (u | 0x80000000u);
}
__device__ __forceinline__ float fdec(unsigned u) {
    return __uint_as_float((u & 0x80000000u) ? (u & 0x7fffffffu) : ~u);
}
__device__ __forceinline__ float leaky(float e) { return e > 0.f ? e : 0.2f * e; }
__device__ __forceinline__ float dot4(float4 a, float4 b) {
    return a.x * b.x + a.y * b.y + a.z * b.z + a.w * b.w;
}

// ---------------- init ----------------------------------------------------------
__global__ void init_kernel(int N) {
    int i = blockIdx.x * blockDim.x + threadIdx.x;
    if (i < N) g_counts[i] = 0;
    if (i < H1) { g_ms1[i] = 0u; g_md1[i] = 0u; }
    if (i == 0) { g_ms2 = 0u; g_md2 = 0u; }
}

// ---------------- GEMM1: 256-node tile, 4 nodes/thread, k-chunked smem ---------
__global__ __launch_bounds__(256, 2)
void gemm1_kernel(const float* __restrict__ x,
                  const float* __restrict__ W1,
                  const float* __restrict__ a_src1,
                  const float* __restrict__ a_dst1,
                  int N) {
    __shared__ float sX[256 * 33];
    __shared__ float sW[32 * 64];
    __shared__ unsigned sMax[16];
    int t = threadIdx.x;
    if (t < 16) sMax[t] = 0u;
    int base = blockIdx.x << 8;
    int nl = t >> 2;
    int q  = t & 3;

    float4 acc[4][4];
#pragma unroll
    for (int i = 0; i < 4; i++)
#pragma unroll
        for (int j = 0; j < 4; j++) acc[i][j] = make_float4(0.f, 0.f, 0.f, 0.f);

    for (int kc = 0; kc < 4; kc++) {
        __syncthreads();
#pragma unroll
        for (int i = 0; i < 2; i++)
            ((float4*)sW)[t + (i << 8)] =
                __ldg((const float4*)(W1 + (kc << 11)) + t + (i << 8));
#pragma unroll
        for (int i = 0; i < 8; i++) {
            int idx = t + (i << 8);
            int node = idx >> 3, k4 = idx & 7;
            int n = base + node;
            float4 v = make_float4(0.f, 0.f, 0.f, 0.f);
            if (n < N) v = __ldg((const float4*)x + ((size_t)n << 5) + (kc << 3) + k4);
            float* dp = &sX[node * 33 + (k4 << 2)];
            dp[0] = v.x; dp[1] = v.y; dp[2] = v.z; dp[3] = v.w;
        }
        __syncthreads();
#pragma unroll 8
        for (int k = 0; k < 32; k++) {
            const float4* wr = (const float4*)&sW[(k << 6) + (q << 4)];
            float4 w0 = wr[0], w1 = wr[1], w2 = wr[2], w3 = wr[3];
#pragma unroll
            for (int i = 0; i < 4; i++) {
                float xv = sX[(nl + (i << 6)) * 33 + k];
                acc[i][0].x += xv * w0.x; acc[i][0].y += xv * w0.y;
                acc[i][0].z += xv * w0.z; acc[i][0].w += xv * w0.w;
                acc[i][1].x += xv * w1.x; acc[i][1].y += xv * w1.y;
                acc[i][1].z += xv * w1.z; acc[i][1].w += xv * w1.w;
                acc[i][2].x += xv * w2.x; acc[i][2].y += xv * w2.y;
                acc[i][2].z += xv * w2.z; acc[i][2].w += xv * w2.w;
                acc[i][3].x += xv * w3.x; acc[i][3].y += xv * w3.y;
                acc[i][3].z += xv * w3.z; acc[i][3].w += xv * w3.w;
            }
        }
    }

    int h0 = q << 1;
    const float4* As4 = (const float4*)a_src1;
    const float4* Ad4 = (const float4*)a_dst1;
    float4 s0 = __ldg(&As4[h0 * 2]),     s1 = __ldg(&As4[h0 * 2 + 1]);
    float4 s2 = __ldg(&As4[h0 * 2 + 2]), s3 = __ldg(&As4[h0 * 2 + 3]);
    float4 d0 = __ldg(&Ad4[h0 * 2]),     d1 = __ldg(&Ad4[h0 * 2 + 1]);
    float4 d2 = __ldg(&Ad4[h0 * 2 + 2]), d3 = __ldg(&Ad4[h0 * 2 + 3]);
#pragma unroll
    for (int i = 0; i < 4; i++) {
        int n = base + nl + (i << 6);
        if (n < N) {
            float4* zr = (float4*)&g_z1[((size_t)n << 6) + (q << 4)];
            zr[0] = acc[i][0]; zr[1] = acc[i][1];
            zr[2] = acc[i][2]; zr[3] = acc[i][3];
            float as0  = dot4(acc[i][0], s0) + dot4(acc[i][1], s1);
            float as1v = dot4(acc[i][2], s2) + dot4(acc[i][3], s3);
            float ad0  = dot4(acc[i][0], d0) + dot4(acc[i][1], d1);
            float ad1v = dot4(acc[i][2], d2) + dot4(acc[i][3], d3);
            g_as1[n * H1 + h0]     = as0;
            g_as1[n * H1 + h0 + 1] = as1v;
            g_ad1[n * H1 + h0]     = ad0;
            g_ad1[n * H1 + h0 + 1] = ad1v;
            atomicMax(&sMax[h0],         fenc(as0));
            atomicMax(&sMax[h0 + 1],     fenc(as1v));
            atomicMax(&sMax[8 + h0],     fenc(ad0));
            atomicMax(&sMax[8 + h0 + 1], fenc(ad1v));
        }
    }
    __syncthreads();
    if (t < 8)        atomicMax(&g_ms1[t], sMax[t]);
    else if (t < 16)  atomicMax(&g_md1[t - 8], sMax[t]);
}

// ---------------- CSR build ----------------------------------------------------
__global__ void hist_kernel(const int* __restrict__ dst, int E) {
    int i = blockIdx.x * blockDim.x + threadIdx.x;
    int i4 = i << 2;
    if (i4 + 3 < E) {
        int4 d = __ldg((const int4*)dst + i);
        atomicAdd(&g_counts[d.x], 1);
        atomicAdd(&g_counts[d.y], 1);
        atomicAdd(&g_counts[d.z], 1);
        atomicAdd(&g_counts[d.w], 1);
    } else {
        for (int j = i4; j < E && j < i4 + 4; j++)
            atomicAdd(&g_counts[dst[j]], 1);
    }
}

__global__ void scanA_kernel(int N) {
    __shared__ int s[256];
    int t = threadIdx.x;
    int i = blockIdx.x * 256 + t;
    s[t] = (i < N) ? g_counts[i] : 0;
    __syncthreads();
#pragma unroll
    for (int off = 128; off > 0; off >>= 1) {
        if (t < off) s[t] += s[t + off];
        __syncthreads();
    }
    if (t == 0) g_bsum[blockIdx.x] = s[0];
}

__global__ void scanB_kernel(int NB) {
    __shared__ int s[256];
    int t = threadIdx.x;
    int v = (t < NB) ? g_bsum[t] : 0;
    s[t] = v;
    __syncthreads();
#pragma unroll
    for (int off = 1; off < 256; off <<= 1) {
        int u = (t >= off) ? s[t - off] : 0;
        __syncthreads();
        s[t] += u;
        __syncthreads();
    }
    if (t < NB) g_boff[t] = s[t] - v;
}

__global__ void scanC_kernel(int N) {
    __shared__ int s[256];
    int t = threadIdx.x;
    int i = blockIdx.x * 256 + t;
    int v = (i < N) ? g_counts[i] : 0;
    s[t] = v;
    __syncthreads();
#pragma unroll
    for (int off = 1; off < 256; off <<= 1) {
        int u = (t >= off) ? s[t - off] : 0;
        __syncthreads();
        s[t] += u;
        __syncthreads();
    }
    int incl = s[t];
    int base = g_boff[blockIdx.x];
    if (i < N) {
        int r = base + incl - v;
        g_rowptr[i] = r;
        g_cursor[i] = r;
        if (i == N - 1) g_rowptr[N] = base + incl;
    }
}

__global__ void scatter_kernel(const int* __restrict__ src,
                               const int* __restrict__ dst, int E) {
    int i = blockIdx.x * blockDim.x + threadIdx.x;
    int i4 = i << 2;
    if (i4 + 3 < E) {
        int4 sv = __ldg((const int4*)src + i);
        int4 dv = __ldg((const int4*)dst + i);
        g_csr[atomicAdd(&g_cursor[dv.x], 1)] = sv.x;
        g_csr[atomicAdd(&g_cursor[dv.y], 1)] = sv.y;
        g_csr[atomicAdd(&g_cursor[dv.z], 1)] = sv.z;
        g_csr[atomicAdd(&g_cursor[dv.w], 1)] = sv.w;
    } else {
        for (int j = i4; j < E && j < i4 + 4; j++)
            g_csr[atomicAdd(&g_cursor[dst[j]], 1)] = src[j];
    }
}

// ---------------- layer-1 aggregation: warp/node, 8 edges per iteration --------
__global__ void agg1_kernel(const float* __restrict__ b1, int N) {
    int w = (blockIdx.x * blockDim.x + threadIdx.x) >> 5;
    int lane = threadIdx.x & 31;
    if (w >= N) return;
    int n = w;
    int h8 = lane & 7;       // attention head
    int grp = lane >> 3;     // attention edge slot (0..3)
    int half = lane >> 4;    // message edge parity
    int c = lane & 15;       // float4 owner (dims 4c..4c+3)
    int hq = c >> 1;         // head of those dims

    float ad_rep = g_ad1[n * H1 + h8];
    float M_rep  = fdec(g_ms1[h8]) + fdec(g_md1[h8]);

    float4 acc = make_float4(0.f, 0.f, 0.f, 0.f);
    float den = 0.f;
    int beg = g_rowptr[n], end = g_rowptr[n + 1];

    for (int i = beg; i < end; i += 8) {
        int ea = i + grp, eb = i + 4 + grp;
        bool va = ea < end, vb = eb < end;
        int s_a = va ? __ldg(&g_csr[ea]) : 0;
        int s_b = vb ? __ldg(&g_csr[eb]) : 0;
        float a_a = va ? __ldg(&g_as1[s_a * H1 + h8]) : 0.f;
        float a_b = vb ? __ldg(&g_as1[s_b * H1 + h8]) : 0.f;

        // broadcast source ids for the 4 message loads this lane does
        int se0 = __shfl_sync(0xffffffffu, s_a, half << 3);         // edge i+half
        int se1 = __shfl_sync(0xffffffffu, s_a, (2 + half) << 3);   // edge i+2+half
        int se2 = __shfl_sync(0xffffffffu, s_b, half << 3);         // edge i+4+half
        int se3 = __shfl_sync(0xffffffffu, s_b, (2 + half) << 3);   // edge i+6+half
        bool v0 = (i + half) < end;
        bool v1 = (i + 2 + half) < end;
        bool v2 = (i + 4 + half) < end;
        bool v3 = (i + 6 + half) < end;
        float4 z0 = v0 ? __ldg((const float4*)&g_z1[((size_t)se0 << 6) + (c << 2)]) : make_float4(0.f,0.f,0.f,0.f);
        float4 z1 = v1 ? __ldg((const float4*)&g_z1[((size_t)se1 << 6) + (c << 2)]) : make_float4(0.f,0.f,0.f,0.f);
        float4 z2 = v2 ? __ldg((const float4*)&g_z1[((size_t)se2 << 6) + (c << 2)]) : make_float4(0.f,0.f,0.f,0.f);
        float4 z3 = v3 ? __ldg((const float4*)&g_z1[((size_t)se3 << 6) + (c << 2)]) : make_float4(0.f,0.f,0.f,0.f);

        float w_a = va ? __expf(leaky(a_a + ad_rep) - M_rep) : 0.f;
        float w_b = vb ? __expf(leaky(a_b + ad_rep) - M_rep) : 0.f;
        den += w_a + w_b;

        float we0 = __shfl_sync(0xffffffffu, w_a, (half << 3) | hq);
        float we1 = __shfl_sync(0xffffffffu, w_a, ((2 + half) << 3) | hq);
        float we2 = __shfl_sync(0xffffffffu, w_b, (half << 3) | hq);
        float we3 = __shfl_sync(0xffffffffu, w_b, ((2 + half) << 3) | hq);

        acc.x += we0 * z0.x + we1 * z1.x + we2 * z2.x + we3 * z3.x;
        acc.y += we0 * z0.y + we1 * z1.y + we2 * z2.y + we3 * z3.y;
        acc.z += we0 * z0.z + we1 * z1.z + we2 * z2.z + we3 * z3.z;
        acc.w += we0 * z0.w + we1 * z1.w + we2 * z2.w + we3 * z3.w;
    }
    // combine message halves
    acc.x += __shfl_xor_sync(0xffffffffu, acc.x, 16);
    acc.y += __shfl_xor_sync(0xffffffffu, acc.y, 16);
    acc.z += __shfl_xor_sync(0xffffffffu, acc.z, 16);
    acc.w += __shfl_xor_sync(0xffffffffu, acc.w, 16);
    // reduce den over edge slots (same head at stride 8)
    den += __shfl_xor_sync(0xffffffffu, den, 8);
    den += __shfl_xor_sync(0xffffffffu, den, 16);
    float dl = __shfl_sync(0xffffffffu, den, hq);

    if (lane < 16) {
        float4 bb = __ldg((const float4*)&b1[c << 2]);
        float inv = 1.f / (dl + 1e-16f);
        float o0 = acc.x * inv + bb.x;
        float o1 = acc.y * inv + bb.y;
        float o2 = acc.z * inv + bb.z;
        float o3 = acc.w * inv + bb.w;
        o0 = o0 > 0.f ? o0 : (__expf(o0) - 1.f);
        o1 = o1 > 0.f ? o1 : (__expf(o1) - 1.f);
        o2 = o2 > 0.f ? o2 : (__expf(o2) - 1.f);
        o3 = o3 > 0.f ? o3 : (__expf(o3) - 1.f);
        *(float4*)&g_h[((size_t)n << 6) + (c << 2)] = make_float4(o0, o1, o2, o3);
    }
}

// ---------------- layer-2 node transform (smem-staged) --------------------------
__global__ void node2_kernel(const float* __restrict__ W2,
                             const float* __restrict__ a_src2,
                             const float* __restrict__ a_dst2,
                             int N) {
    __shared__ float sH[16 * 64];
    __shared__ float sW2[64 * 16];
    __shared__ unsigned smS, smD;
    int t = threadIdx.x;
    if (t == 0) { smS = 0u; smD = 0u; }
    int base = blockIdx.x << 4;
    {
        int node = t >> 4, k4 = t & 15;
        int nn = base + node;
        float4 v = make_float4(0.f, 0.f, 0.f, 0.f);
        if (nn < N) v = __ldg((const float4*)&g_h[((size_t)nn << 6) + (k4 << 2)]);
        *(float4*)&sH[(node << 6) + (k4 << 2)] = v;
        ((float4*)sW2)[t] = __ldg((const float4*)W2 + t);
    }
    __syncthreads();

    int nl = t >> 4, c = t & 15;
    int n = base + nl;
    float acc = 0.f;
#pragma unroll 16
    for (int k = 0; k < 64; k++)
        acc += sH[(nl << 6) + k] * sW2[(k << 4) + c];

    float ts = acc * __ldg(&a_src2[c]);
    float td = acc * __ldg(&a_dst2[c]);
#pragma unroll
    for (int off = 8; off > 0; off >>= 1) {
        ts += __shfl_xor_sync(0xffffffffu, ts, off, 16);
        td += __shfl_xor_sync(0xffffffffu, td, off, 16);
    }
    if (n < N) {
        g_z2[n * D2 + c] = acc;
        if (c == 0) {
            g_as2[n] = ts;
            g_ad2[n] = td;
            atomicMax(&smS, fenc(ts));
            atomicMax(&smD, fenc(td));
        }
    }
    __syncthreads();
    if (t == 0) {
        atomicMax(&g_ms2, smS);
        atomicMax(&g_md2, smD);
    }
}

// ---------------- layer-2 aggregation: warp/node, 16 edges per iteration --------
__global__ void agg2_kernel(const float* __restrict__ b2,
                            float* __restrict__ out, int N) {
    int w = (blockIdx.x * blockDim.x + threadIdx.x) >> 5;
    int lane = threadIdx.x & 31;
    if (w >= N) return;
    int n = w;
    int el = lane & 15;      // attention edge slot (duplicated on high half)
    int g8 = lane >> 2;      // message edge-in-phase (0..7)
    int cq = lane & 3;       // float4 owner

    float M2  = fdec(g_ms2) + fdec(g_md2);
    float adl = g_ad2[n];
    float4 acc = make_float4(0.f, 0.f, 0.f, 0.f);
    float den = 0.f;
    int beg = g_rowptr[n], end = g_rowptr[n + 1];

    for (int i = beg; i < end; i += 16) {
        int e = i + el;
        bool v = e < end;
        int s_l = v ? __ldg(&g_csr[e]) : 0;
        float a = v ? __ldg(&g_as2[s_l]) : 0.f;

        int se0 = __shfl_sync(0xffffffffu, s_l, g8);        // edge i+g8
        int se1 = __shfl_sync(0xffffffffu, s_l, 8 + g8);    // edge i+8+g8
        bool v0 = (i + g8) < end;
        bool v1 = (i + 8 + g8) < end;
        float4 z0 = v0 ? __ldg((const float4*)&g_z2[(size_t)se0 * D2 + (cq << 2)]) : make_float4(0.f,0.f,0.f,0.f);
        float4 z1 = v1 ? __ldg((const float4*)&g_z2[(size_t)se1 * D2 + (cq << 2)]) : make_float4(0.f,0.f,0.f,0.f);

        float wv = v ? __expf(leaky(a + adl) - M2) : 0.f;
        if (lane < 16) den += wv;

        float we0 = __shfl_sync(0xffffffffu, wv, g8);
        float we1 = __shfl_sync(0xffffffffu, wv, 8 + g8);
        acc.x += we0 * z0.x + we1 * z1.x;
        acc.y += we0 * z0.y + we1 * z1.y;
        acc.z += we0 * z0.z + we1 * z1.z;
        acc.w += we0 * z0.w + we1 * z1.w;
    }
#pragma unroll
    for (int off = 4; off < 32; off <<= 1) {
        acc.x += __shfl_xor_sync(0xffffffffu, acc.x, off);
        acc.y += __shfl_xor_sync(0xffffffffu, acc.y, off);
        acc.z += __shfl_xor_sync(0xffffffffu, acc.z, off);
        acc.w += __shfl_xor_sync(0xffffffffu, acc.w, off);
    }
    den += __shfl_xor_sync(0xffffffffu, den, 1);
    den += __shfl_xor_sync(0xffffffffu, den, 2);
    den += __shfl_xor_sync(0xffffffffu, den, 4);
    den += __shfl_xor_sync(0xffffffffu, den, 8);
    den = __shfl_sync(0xffffffffu, den, 0);

    if (lane < 4) {
        float4 bb = __ldg((const float4*)&b2[cq << 2]);
        float inv = 1.f / (den + 1e-16f);
        float4 o = make_float4(acc.x * inv + bb.x, acc.y * inv + bb.y,
                               acc.z * inv + bb.z, acc.w * inv + bb.w);
        *(float4*)&out[(size_t)n * D2 + (cq << 2)] = o;
    }
}

// ---------------- launch: forked capture (gemm1 || CSR build) -------------------
static inline int cdiv(int a, int b) { return (a + b - 1) / b; }

extern "C" void kernel_launch(void* const* d_in, const int* in_sizes, int n_in,
                              void* d_out, int out_size) {
    const float* x   = (const float*)d_in[0];
    const int*   ei  = (const int*)d_in[1];
    const float* W1  = (const float*)d_in[2];
    const float* as1 = (const float*)d_in[3];
    const float* ad1 = (const float*)d_in[4];
    const float* b1  = (const float*)d_in[5];
    const float* W2  = (const float*)d_in[6];
    const float* as2 = (const float*)d_in[7];
    const float* ad2 = (const float*)d_in[8];
    const float* b2  = (const float*)d_in[9];
    float* out = (float*)d_out;

    int N = in_sizes[0] / DIN;
    int E = in_sizes[1] / 2;
    const int* src = ei;
    const int* dst = ei + E;
    int NB = cdiv(N, 256);
    int E4 = cdiv(E, 4);

    // one-time infra (streams/events are not device memory)
    static cudaStream_t s_side = nullptr;
    static cudaEvent_t ev_fork = nullptr, ev_join = nullptr;
    if (!s_side) {
        cudaStreamCreateWithFlags(&s_side, cudaStreamNonBlocking);
        cudaEventCreateWithFlags(&ev_fork, cudaEventDisableTiming);
        cudaEventCreateWithFlags(&ev_join, cudaEventDisableTiming);
    }

    init_kernel<<<cdiv(N, 256), 256>>>(N);
    cudaEventRecord(ev_fork, 0);
    cudaStreamWaitEvent(s_side, ev_fork, 0);

    // side branch: CSR build (reads only edges + counts)
    hist_kernel<<<cdiv(E4, 256), 256, 0, s_side>>>(dst, E);
    scanA_kernel<<<NB, 256, 0, s_side>>>(N);
    scanB_kernel<<<1, 256, 0, s_side>>>(NB);
    scanC_kernel<<<NB, 256, 0, s_side>>>(N);
    scatter_kernel<<<cdiv(E4, 256), 256, 0, s_side>>>(src, dst, E);
    cudaEventRecord(ev_join, s_side);

    // main branch: feature transform
    gemm1_kernel<<<cdiv(N, 256), 256>>>(x, W1, as1, ad1, N);

    // join, then aggregation chain
    cudaStreamWaitEvent(0, ev_join, 0);
    agg1_kernel<<<cdiv(N * 32, 256), 256>>>(b1, N);
    node2_kernel<<<cdiv(N, 16), 256>>>(W2, as2, ad2, N);
    agg2_kernel<<<cdiv(N * 32, 256), 256>>>(b2, out, N);
}